// round 13
// baseline (speedup 1.0000x reference)
#include <cuda_runtime.h>
#include <cstdint>

#define BATCH 256
#define TSTEPS 1024
#define HID 64
#define DIN 3

typedef unsigned long long u64;

// ---- packed fp32x2 helpers (ptxas never auto-emits FFMA2) ----
__device__ __forceinline__ u64 fma2(u64 a, u64 b, u64 c) {
    u64 d; asm("fma.rn.f32x2 %0, %1, %2, %3;" : "=l"(d) : "l"(a), "l"(b), "l"(c)); return d;
}
__device__ __forceinline__ u64 packf2(float lo, float hi) {
    u64 d; asm("mov.b64 %0, {%1, %2};" : "=l"(d) : "f"(lo), "f"(hi)); return d;
}
__device__ __forceinline__ float2 unpackf2(u64 v) {
    float2 f; asm("mov.b64 {%0, %1}, %2;" : "=f"(f.x), "=f"(f.y) : "l"(v)); return f;
}
__device__ __forceinline__ void lds2(u64 &a, u64 &b, uint32_t addr) {
    asm volatile("ld.shared.v2.b64 {%0, %1}, [%2];" : "=l"(a), "=l"(b) : "r"(addr));
}

// ---- single-MUFU activations (tanh.approx) ----
__device__ __forceinline__ float tanha(float x) {
    float r; asm("tanh.approx.f32 %0, %1;" : "=f"(r) : "f"(x)); return r;
}
__device__ __forceinline__ float siga(float x) {
    return fmaf(0.5f, tanha(0.5f * x), 0.5f);
}
// fire-and-forget global fp32 reduction (REDG: no return, no fence)
__device__ __forceinline__ void redadd(float* p, float v) {
    asm volatile("red.global.add.f32 [%0], %1;" :: "l"(p), "f"(v) : "memory");
}

// ============================================================================
// y init: y[r*3+o] = bout[o]  (REDG accumulation target)
// ============================================================================
__global__ void __launch_bounds__(256) init_y(
    const float* __restrict__ bout, float* __restrict__ y)
{
    __shared__ float sb[3];
    if (threadIdx.x < 3) sb[threadIdx.x] = bout[threadIdx.x];
    __syncthreads();
    int i = blockIdx.x * 256 + threadIdx.x;           // 786432 total
    int o = i - (i / 3) * 3;
    y[i] = sb[o];
}

// ============================================================================
// Fused 2-layer LSTM — round-10 champion (799.8us) with the projection folded
// into the l2 cell phase via red.global.add (3 REDG per l2 cell per step).
// g_h2 scratch and the separate projection kernel are deleted.
// One CTA per 2 sequences, 256 threads. Thread j owns gate row j of
// Whh0, Wih1, Whh1 (registers). Pipeline: iter t = l1 step t, l2 step t-1.
// sh1 = h1[t-1], sh2 = h2[t-2]; 2 barriers/step; 256 threads = 256 cells.
// ============================================================================
__global__ void __launch_bounds__(256, 1) lstm_fused(
    const float* __restrict__ x,
    const float* __restrict__ Wih0, const float* __restrict__ Whh0,
    const float* __restrict__ bih0, const float* __restrict__ bhh0,
    const float* __restrict__ Wih1, const float* __restrict__ Whh1,
    const float* __restrict__ bih1, const float* __restrict__ bhh1,
    const float* __restrict__ Wout, float* __restrict__ y)
{
    __shared__ __align__(16) float sx[2][TSTEPS * DIN];  // 24 KB
    __shared__ __align__(16) float sh1[2][HID];
    __shared__ __align__(16) float sh2[2][HID];
    __shared__ __align__(16) float sg1[2][256];
    __shared__ __align__(16) float sg2[2][256];
    const int tid = threadIdx.x;
    const int b0 = blockIdx.x * 2;

    // stage both sequences' inputs
    {
        const float4* xs0 = (const float4*)(x + (size_t)b0 * TSTEPS * DIN);
        const float4* xs1 = (const float4*)(x + (size_t)(b0 + 1) * TSTEPS * DIN);
        #pragma unroll
        for (int i = 0; i < 3; i++) {
            int idx = tid + i * 256;
            ((float4*)sx[0])[idx] = xs0[idx];
            ((float4*)sx[1])[idx] = xs1[idx];
        }
    }

    // per-thread weight rows, packed f32x2 along k
    u64 w0[32], wA[32], wB[32];
    {
        const float4* r0 = (const float4*)(Whh0 + tid * HID);
        const float4* rA = (const float4*)(Wih1 + tid * HID);
        const float4* rB = (const float4*)(Whh1 + tid * HID);
        #pragma unroll
        for (int i = 0; i < 16; i++) {
            float4 v = r0[i]; w0[2*i] = packf2(v.x, v.y); w0[2*i+1] = packf2(v.z, v.w);
            float4 a = rA[i]; wA[2*i] = packf2(a.x, a.y); wA[2*i+1] = packf2(a.z, a.w);
            float4 b = rB[i]; wB[2*i] = packf2(b.x, b.y); wB[2*i+1] = packf2(b.z, b.w);
        }
    }
    const float wx0 = Wih0[tid * 3 + 0], wx1 = Wih0[tid * 3 + 1], wx2 = Wih0[tid * 3 + 2];
    const float bias0 = bih0[tid] + bhh0[tid];
    const float bias1 = bih1[tid] + bhh1[tid];
    const int gtype = tid >> 6;

    // cell role: tid -> (layer, seq, m)
    const int cl_layer = tid >> 7;
    const int cl_b = (tid >> 6) & 1;
    const int cl_m = tid & 63;
    float c = 0.0f;

    // projection weights for my l2 cell (only used by cl_layer==1 threads)
    const float pw0 = Wout[cl_m];
    const float pw1 = Wout[64 + cl_m];
    const float pw2 = Wout[128 + cl_m];
    float* ybase = y + (size_t)(b0 + cl_b) * TSTEPS * 3;

    if (tid < 128) ((float*)sh1)[tid] = 0.0f;
    else           ((float*)sh2)[tid - 128] = 0.0f;

    const uint32_t a_h1s0 = (uint32_t)__cvta_generic_to_shared(&sh1[0][0]);
    const uint32_t a_h1s1 = (uint32_t)__cvta_generic_to_shared(&sh1[1][0]);
    const uint32_t a_h2s0 = (uint32_t)__cvta_generic_to_shared(&sh2[0][0]);
    const uint32_t a_h2s1 = (uint32_t)__cvta_generic_to_shared(&sh2[1][0]);
    __syncthreads();

    #pragma unroll 1
    for (int t = 0; t <= TSTEPS; t++) {
        // ---- gate phase: 6 dot products, 192 fma2, 64 LDS.128 (all broadcast)
        u64 A0 = 0, A1 = 0, B0 = 0, B1 = 0, C0 = 0, C1 = 0;
        #pragma unroll
        for (int kk = 0; kk < 16; kk++) {
            u64 p0, p1, q0, q1, r0, r1, s0, s1;
            lds2(p0, p1, a_h1s0 + kk * 16);
            lds2(q0, q1, a_h1s1 + kk * 16);
            lds2(r0, r1, a_h2s0 + kk * 16);
            lds2(s0, s1, a_h2s1 + kk * 16);
            A0 = fma2(w0[2*kk],     p0, A0);
            A0 = fma2(w0[2*kk + 1], p1, A0);
            A1 = fma2(w0[2*kk],     q0, A1);
            A1 = fma2(w0[2*kk + 1], q1, A1);
            B0 = fma2(wA[2*kk],     p0, B0);
            B0 = fma2(wA[2*kk + 1], p1, B0);
            B1 = fma2(wA[2*kk],     q0, B1);
            B1 = fma2(wA[2*kk + 1], q1, B1);
            C0 = fma2(wB[2*kk],     r0, C0);
            C0 = fma2(wB[2*kk + 1], r1, C0);
            C1 = fma2(wB[2*kk],     s0, C1);
            C1 = fma2(wB[2*kk + 1], s1, C1);
        }
        const int tx = (t < TSTEPS) ? t : (TSTEPS - 1);
        float xa0 = sx[0][tx*3 + 0], xa1 = sx[0][tx*3 + 1], xa2 = sx[0][tx*3 + 2];
        float xb0 = sx[1][tx*3 + 0], xb1 = sx[1][tx*3 + 1], xb2 = sx[1][tx*3 + 2];
        float2 fA0 = unpackf2(A0), fA1 = unpackf2(A1);
        float2 fB0 = unpackf2(B0), fB1 = unpackf2(B1);
        float2 fC0 = unpackf2(C0), fC1 = unpackf2(C1);
        float pre10 = fA0.x + fA0.y + bias0 + wx0*xa0 + wx1*xa1 + wx2*xa2;
        float pre11 = fA1.x + fA1.y + bias0 + wx0*xb0 + wx1*xb1 + wx2*xb2;
        float pre20 = (fB0.x + fB0.y) + (fC0.x + fC0.y) + bias1;
        float pre21 = (fB1.x + fB1.y) + (fC1.x + fC1.y) + bias1;
        float v10, v11, v20, v21;
        if (gtype == 2) {
            v10 = tanha(pre10); v11 = tanha(pre11);
            v20 = tanha(pre20); v21 = tanha(pre21);
        } else {
            v10 = siga(pre10); v11 = siga(pre11);
            v20 = siga(pre20); v21 = siga(pre21);
        }
        sg1[0][tid] = v10; sg1[1][tid] = v11;
        sg2[0][tid] = v20; sg2[1][tid] = v21;
        __syncthreads();

        // ---- cell phase: one cell per thread (warp-uniform roles) ----
        bool active = cl_layer ? (t >= 1) : (t < TSTEPS);
        if (active) {
            const float* Gp = cl_layer ? sg2[cl_b] : sg1[cl_b];
            float iv = Gp[cl_m], fv = Gp[cl_m + 64];
            float gv = Gp[cl_m + 128], ov = Gp[cl_m + 192];
            c = fmaf(fv, c, iv * gv);
            float hn = ov * tanha(c);
            if (cl_layer) {
                sh2[cl_b][cl_m] = hn;
                // projection contribution: fire-and-forget REDG x3
                float* yp = ybase + (size_t)(t - 1) * 3;
                redadd(yp + 0, hn * pw0);
                redadd(yp + 1, hn * pw1);
                redadd(yp + 2, hn * pw2);
            } else {
                sh1[cl_b][cl_m] = hn;
            }
        }
        __syncthreads();
    }
}

extern "C" void kernel_launch(void* const* d_in, const int* in_sizes, int n_in,
                              void* d_out, int out_size)
{
    const float* x    = (const float*)d_in[0];
    const float* Wih0 = (const float*)d_in[1];
    const float* Whh0 = (const float*)d_in[2];
    const float* bih0 = (const float*)d_in[3];
    const float* bhh0 = (const float*)d_in[4];
    const float* Wih1 = (const float*)d_in[5];
    const float* Whh1 = (const float*)d_in[6];
    const float* bih1 = (const float*)d_in[7];
    const float* bhh1 = (const float*)d_in[8];
    const float* Wout = (const float*)d_in[9];
    const float* bout = (const float*)d_in[10];
    float* y = (float*)d_out;

    init_y<<<(BATCH * TSTEPS * 3) / 256, 256>>>(bout, y);
    lstm_fused<<<BATCH / 2, 256>>>(x, Wih0, Whh0, bih0, bhh0,
                                   Wih1, Whh1, bih1, bhh1,
                                   Wout, y);
}

// round 14
// speedup vs baseline: 1.0733x; 1.0733x over previous
#include <cuda_runtime.h>
#include <cuda_fp16.h>
#include <cstdint>

#define BATCH 256
#define TSTEPS 1024
#define HID 64
#define DIN 3

// Scratch (device globals — no cudaMalloc allowed). h2 as fp16: halves proj
// traffic; measured error contribution 9.8e-5 on y (R9), well under 1e-3.
__device__ __half g_h2[BATCH * TSTEPS * HID];

typedef unsigned long long u64;

// ---- packed fp32x2 helpers (ptxas never auto-emits FFMA2) ----
__device__ __forceinline__ u64 fma2(u64 a, u64 b, u64 c) {
    u64 d; asm("fma.rn.f32x2 %0, %1, %2, %3;" : "=l"(d) : "l"(a), "l"(b), "l"(c)); return d;
}
__device__ __forceinline__ u64 packf2(float lo, float hi) {
    u64 d; asm("mov.b64 %0, {%1, %2};" : "=l"(d) : "f"(lo), "f"(hi)); return d;
}
__device__ __forceinline__ float2 unpackf2(u64 v) {
    float2 f; asm("mov.b64 {%0, %1}, %2;" : "=f"(f.x), "=f"(f.y) : "l"(v)); return f;
}
__device__ __forceinline__ void lds2(u64 &a, u64 &b, uint32_t addr) {
    asm volatile("ld.shared.v2.b64 {%0, %1}, [%2];" : "=l"(a), "=l"(b) : "r"(addr));
}

// ---- single-MUFU activations (tanh.approx) ----
__device__ __forceinline__ float tanha(float x) {
    float r; asm("tanh.approx.f32 %0, %1;" : "=f"(r) : "f"(x)); return r;
}
__device__ __forceinline__ float siga(float x) {
    return fmaf(0.5f, tanha(0.5f * x), 0.5f);
}

// ============================================================================
// Fused 2-layer LSTM — round-10 champion (799.8us), unchanged except h2 is
// written to global as fp16. One CTA per 2 sequences, 256 threads.
// Thread j owns gate row j of Whh0, Wih1, Whh1 (registers).
// Pipeline: iter t = l1 step t, l2 step t-1. sh1 = h1[t-1], sh2 = h2[t-2].
// 2 barriers/step; cell phase: 256 threads = 256 cells.
// ============================================================================
__global__ void __launch_bounds__(256, 1) lstm_fused(
    const float* __restrict__ x,
    const float* __restrict__ Wih0, const float* __restrict__ Whh0,
    const float* __restrict__ bih0, const float* __restrict__ bhh0,
    const float* __restrict__ Wih1, const float* __restrict__ Whh1,
    const float* __restrict__ bih1, const float* __restrict__ bhh1)
{
    __shared__ __align__(16) float sx[2][TSTEPS * DIN];  // 24 KB
    __shared__ __align__(16) float sh1[2][HID];
    __shared__ __align__(16) float sh2[2][HID];
    __shared__ __align__(16) float sg1[2][256];
    __shared__ __align__(16) float sg2[2][256];
    const int tid = threadIdx.x;
    const int b0 = blockIdx.x * 2;

    // stage both sequences' inputs
    {
        const float4* xs0 = (const float4*)(x + (size_t)b0 * TSTEPS * DIN);
        const float4* xs1 = (const float4*)(x + (size_t)(b0 + 1) * TSTEPS * DIN);
        #pragma unroll
        for (int i = 0; i < 3; i++) {
            int idx = tid + i * 256;
            ((float4*)sx[0])[idx] = xs0[idx];
            ((float4*)sx[1])[idx] = xs1[idx];
        }
    }

    // per-thread weight rows, packed f32x2 along k
    u64 w0[32], wA[32], wB[32];
    {
        const float4* r0 = (const float4*)(Whh0 + tid * HID);
        const float4* rA = (const float4*)(Wih1 + tid * HID);
        const float4* rB = (const float4*)(Whh1 + tid * HID);
        #pragma unroll
        for (int i = 0; i < 16; i++) {
            float4 v = r0[i]; w0[2*i] = packf2(v.x, v.y); w0[2*i+1] = packf2(v.z, v.w);
            float4 a = rA[i]; wA[2*i] = packf2(a.x, a.y); wA[2*i+1] = packf2(a.z, a.w);
            float4 b = rB[i]; wB[2*i] = packf2(b.x, b.y); wB[2*i+1] = packf2(b.z, b.w);
        }
    }
    const float wx0 = Wih0[tid * 3 + 0], wx1 = Wih0[tid * 3 + 1], wx2 = Wih0[tid * 3 + 2];
    const float bias0 = bih0[tid] + bhh0[tid];
    const float bias1 = bih1[tid] + bhh1[tid];
    const int gtype = tid >> 6;

    // cell role: tid -> (layer, seq, m)
    const int cl_layer = tid >> 7;
    const int cl_b = (tid >> 6) & 1;
    const int cl_m = tid & 63;
    float c = 0.0f;

    if (tid < 128) ((float*)sh1)[tid] = 0.0f;
    else           ((float*)sh2)[tid - 128] = 0.0f;

    const uint32_t a_h1s0 = (uint32_t)__cvta_generic_to_shared(&sh1[0][0]);
    const uint32_t a_h1s1 = (uint32_t)__cvta_generic_to_shared(&sh1[1][0]);
    const uint32_t a_h2s0 = (uint32_t)__cvta_generic_to_shared(&sh2[0][0]);
    const uint32_t a_h2s1 = (uint32_t)__cvta_generic_to_shared(&sh2[1][0]);
    __half* h2out = &g_h2[(size_t)(b0 + cl_b) * TSTEPS * HID + cl_m];
    __syncthreads();

    #pragma unroll 1
    for (int t = 0; t <= TSTEPS; t++) {
        // ---- gate phase: 6 dot products, 192 fma2, 64 LDS.128 (all broadcast)
        u64 A0 = 0, A1 = 0, B0 = 0, B1 = 0, C0 = 0, C1 = 0;
        #pragma unroll
        for (int kk = 0; kk < 16; kk++) {
            u64 p0, p1, q0, q1, r0, r1, s0, s1;
            lds2(p0, p1, a_h1s0 + kk * 16);
            lds2(q0, q1, a_h1s1 + kk * 16);
            lds2(r0, r1, a_h2s0 + kk * 16);
            lds2(s0, s1, a_h2s1 + kk * 16);
            A0 = fma2(w0[2*kk],     p0, A0);
            A0 = fma2(w0[2*kk + 1], p1, A0);
            A1 = fma2(w0[2*kk],     q0, A1);
            A1 = fma2(w0[2*kk + 1], q1, A1);
            B0 = fma2(wA[2*kk],     p0, B0);
            B0 = fma2(wA[2*kk + 1], p1, B0);
            B1 = fma2(wA[2*kk],     q0, B1);
            B1 = fma2(wA[2*kk + 1], q1, B1);
            C0 = fma2(wB[2*kk],     r0, C0);
            C0 = fma2(wB[2*kk + 1], r1, C0);
            C1 = fma2(wB[2*kk],     s0, C1);
            C1 = fma2(wB[2*kk + 1], s1, C1);
        }
        const int tx = (t < TSTEPS) ? t : (TSTEPS - 1);
        float xa0 = sx[0][tx*3 + 0], xa1 = sx[0][tx*3 + 1], xa2 = sx[0][tx*3 + 2];
        float xb0 = sx[1][tx*3 + 0], xb1 = sx[1][tx*3 + 1], xb2 = sx[1][tx*3 + 2];
        float2 fA0 = unpackf2(A0), fA1 = unpackf2(A1);
        float2 fB0 = unpackf2(B0), fB1 = unpackf2(B1);
        float2 fC0 = unpackf2(C0), fC1 = unpackf2(C1);
        float pre10 = fA0.x + fA0.y + bias0 + wx0*xa0 + wx1*xa1 + wx2*xa2;
        float pre11 = fA1.x + fA1.y + bias0 + wx0*xb0 + wx1*xb1 + wx2*xb2;
        float pre20 = (fB0.x + fB0.y) + (fC0.x + fC0.y) + bias1;
        float pre21 = (fB1.x + fB1.y) + (fC1.x + fC1.y) + bias1;
        float v10, v11, v20, v21;
        if (gtype == 2) {
            v10 = tanha(pre10); v11 = tanha(pre11);
            v20 = tanha(pre20); v21 = tanha(pre21);
        } else {
            v10 = siga(pre10); v11 = siga(pre11);
            v20 = siga(pre20); v21 = siga(pre21);
        }
        sg1[0][tid] = v10; sg1[1][tid] = v11;
        sg2[0][tid] = v20; sg2[1][tid] = v21;
        __syncthreads();

        // ---- cell phase: one cell per thread (warp-uniform roles) ----
        bool active = cl_layer ? (t >= 1) : (t < TSTEPS);
        if (active) {
            const float* Gp = cl_layer ? sg2[cl_b] : sg1[cl_b];
            float iv = Gp[cl_m], fv = Gp[cl_m + 64];
            float gv = Gp[cl_m + 128], ov = Gp[cl_m + 192];
            c = fmaf(fv, c, iv * gv);
            float hn = ov * tanha(c);
            if (cl_layer) {
                sh2[cl_b][cl_m] = hn;
                h2out[(size_t)(t - 1) * HID] = __float2half(hn);
            } else {
                sh1[cl_b][cl_m] = hn;
            }
        }
        __syncthreads();
    }
}

// ============================================================================
// Output projection, MLP=8: each thread owns one 16B segment (8 halves) of
// 8 different rows, all loads issued up front (8 independent LDG.128), then
// 8x {3 dots + 8-lane shuffle reduce + store}. 1024 CTAs x 256 threads.
// ============================================================================
#define PROJ_GROUPS (BATCH * TSTEPS / 8)   // 32768 row-groups
__global__ void __launch_bounds__(256) proj_kernel(
    const float* __restrict__ Wout, const float* __restrict__ bout,
    float* __restrict__ y)
{
    __shared__ float sw[3 * 64];
    __shared__ float sb[3];
    const int tid = threadIdx.x;
    if (tid < 192) sw[tid] = Wout[tid];
    if (tid < 3)   sb[tid] = bout[tid];
    __syncthreads();

    const int gg = blockIdx.x * 256 + tid;   // 262144 threads
    const int grp = gg >> 3;                  // row base 0..32767
    const int l = gg & 7;                     // 8 lanes per row

    // issue all 8 loads (independent -> MLP=8)
    uint4 hv[8];
    #pragma unroll
    for (int k = 0; k < 8; k++) {
        size_t r = (size_t)grp + (size_t)k * PROJ_GROUPS;
        hv[k] = *(const uint4*)((const char*)g_h2 + r * 128 + l * 16);
    }

    const int k0 = l * 8;
    const float* w0r = &sw[k0];
    const float* w1r = &sw[64 + k0];
    const float* w2r = &sw[128 + k0];

    #pragma unroll
    for (int k = 0; k < 8; k++) {
        float2 h0 = __half22float2(*(const __half2*)&hv[k].x);
        float2 h1 = __half22float2(*(const __half2*)&hv[k].y);
        float2 h2v = __half22float2(*(const __half2*)&hv[k].z);
        float2 h3 = __half22float2(*(const __half2*)&hv[k].w);
        float a0 = w0r[0]*h0.x + w0r[1]*h0.y + w0r[2]*h1.x + w0r[3]*h1.y
                 + w0r[4]*h2v.x + w0r[5]*h2v.y + w0r[6]*h3.x + w0r[7]*h3.y;
        float a1 = w1r[0]*h0.x + w1r[1]*h0.y + w1r[2]*h1.x + w1r[3]*h1.y
                 + w1r[4]*h2v.x + w1r[5]*h2v.y + w1r[6]*h3.x + w1r[7]*h3.y;
        float a2 = w2r[0]*h0.x + w2r[1]*h0.y + w2r[2]*h1.x + w2r[3]*h1.y
                 + w2r[4]*h2v.x + w2r[5]*h2v.y + w2r[6]*h3.x + w2r[7]*h3.y;
        #pragma unroll
        for (int o = 4; o > 0; o >>= 1) {
            a0 += __shfl_xor_sync(0xffffffffu, a0, o);
            a1 += __shfl_xor_sync(0xffffffffu, a1, o);
            a2 += __shfl_xor_sync(0xffffffffu, a2, o);
        }
        if (l == 0) {
            size_t r = (size_t)grp + (size_t)k * PROJ_GROUPS;
            y[r * 3 + 0] = a0 + sb[0];
            y[r * 3 + 1] = a1 + sb[1];
            y[r * 3 + 2] = a2 + sb[2];
        }
    }
}

extern "C" void kernel_launch(void* const* d_in, const int* in_sizes, int n_in,
                              void* d_out, int out_size)
{
    const float* x    = (const float*)d_in[0];
    const float* Wih0 = (const float*)d_in[1];
    const float* Whh0 = (const float*)d_in[2];
    const float* bih0 = (const float*)d_in[3];
    const float* bhh0 = (const float*)d_in[4];
    const float* Wih1 = (const float*)d_in[5];
    const float* Whh1 = (const float*)d_in[6];
    const float* bih1 = (const float*)d_in[7];
    const float* bhh1 = (const float*)d_in[8];
    const float* Wout = (const float*)d_in[9];
    const float* bout = (const float*)d_in[10];
    float* y = (float*)d_out;

    lstm_fused<<<BATCH / 2, 256>>>(x, Wih0, Whh0, bih0, bhh0,
                                   Wih1, Whh1, bih1, bhh1);
    proj_kernel<<<(BATCH * TSTEPS) / 8 / 32, 256>>>(Wout, bout, y);
}

// round 15
// speedup vs baseline: 1.1442x; 1.0661x over previous
#include <cuda_runtime.h>
#include <cstdint>

#define BATCH 256
#define TSTEPS 1024
#define HID 64
#define DIN 3

// Scratch (device globals — no cudaMalloc allowed). fp32: the fp16 variant
// costs ~56us in the fused cell phase (R14) — more than it saves in proj.
__device__ float g_h2[BATCH * TSTEPS * HID];

typedef unsigned long long u64;

// ---- packed fp32x2 helpers (ptxas never auto-emits FFMA2) ----
__device__ __forceinline__ u64 fma2(u64 a, u64 b, u64 c) {
    u64 d; asm("fma.rn.f32x2 %0, %1, %2, %3;" : "=l"(d) : "l"(a), "l"(b), "l"(c)); return d;
}
__device__ __forceinline__ u64 packf2(float lo, float hi) {
    u64 d; asm("mov.b64 %0, {%1, %2};" : "=l"(d) : "f"(lo), "f"(hi)); return d;
}
__device__ __forceinline__ float2 unpackf2(u64 v) {
    float2 f; asm("mov.b64 {%0, %1}, %2;" : "=f"(f.x), "=f"(f.y) : "l"(v)); return f;
}
__device__ __forceinline__ void lds2(u64 &a, u64 &b, uint32_t addr) {
    asm volatile("ld.shared.v2.b64 {%0, %1}, [%2];" : "=l"(a), "=l"(b) : "r"(addr));
}

// ---- single-MUFU activations (tanh.approx) ----
__device__ __forceinline__ float tanha(float x) {
    float r; asm("tanh.approx.f32 %0, %1;" : "=f"(r) : "f"(x)); return r;
}
__device__ __forceinline__ float siga(float x) {
    return fmaf(0.5f, tanha(0.5f * x), 0.5f);
}

// ============================================================================
// Fused 2-layer LSTM — EXACT round-10 champion (777us fused, byte-identical).
// One CTA per 2 sequences, 256 threads. Thread j owns gate row j of
// Whh0, Wih1, Whh1 (registers). Pipeline: iter t = l1 step t, l2 step t-1.
// sh1 = h1[t-1], sh2 = h2[t-2]; 2 barriers/step; 256 threads = 256 cells.
// ============================================================================
__global__ void __launch_bounds__(256, 1) lstm_fused(
    const float* __restrict__ x,
    const float* __restrict__ Wih0, const float* __restrict__ Whh0,
    const float* __restrict__ bih0, const float* __restrict__ bhh0,
    const float* __restrict__ Wih1, const float* __restrict__ Whh1,
    const float* __restrict__ bih1, const float* __restrict__ bhh1)
{
    __shared__ __align__(16) float sx[2][TSTEPS * DIN];  // 24 KB
    __shared__ __align__(16) float sh1[2][HID];
    __shared__ __align__(16) float sh2[2][HID];
    __shared__ __align__(16) float sg1[2][256];
    __shared__ __align__(16) float sg2[2][256];
    const int tid = threadIdx.x;
    const int b0 = blockIdx.x * 2;

    // stage both sequences' inputs
    {
        const float4* xs0 = (const float4*)(x + (size_t)b0 * TSTEPS * DIN);
        const float4* xs1 = (const float4*)(x + (size_t)(b0 + 1) * TSTEPS * DIN);
        #pragma unroll
        for (int i = 0; i < 3; i++) {
            int idx = tid + i * 256;
            ((float4*)sx[0])[idx] = xs0[idx];
            ((float4*)sx[1])[idx] = xs1[idx];
        }
    }

    // per-thread weight rows, packed f32x2 along k
    u64 w0[32], wA[32], wB[32];
    {
        const float4* r0 = (const float4*)(Whh0 + tid * HID);
        const float4* rA = (const float4*)(Wih1 + tid * HID);
        const float4* rB = (const float4*)(Whh1 + tid * HID);
        #pragma unroll
        for (int i = 0; i < 16; i++) {
            float4 v = r0[i]; w0[2*i] = packf2(v.x, v.y); w0[2*i+1] = packf2(v.z, v.w);
            float4 a = rA[i]; wA[2*i] = packf2(a.x, a.y); wA[2*i+1] = packf2(a.z, a.w);
            float4 b = rB[i]; wB[2*i] = packf2(b.x, b.y); wB[2*i+1] = packf2(b.z, b.w);
        }
    }
    const float wx0 = Wih0[tid * 3 + 0], wx1 = Wih0[tid * 3 + 1], wx2 = Wih0[tid * 3 + 2];
    const float bias0 = bih0[tid] + bhh0[tid];
    const float bias1 = bih1[tid] + bhh1[tid];
    const int gtype = tid >> 6;

    // cell role: tid -> (layer, seq, m)
    const int cl_layer = tid >> 7;
    const int cl_b = (tid >> 6) & 1;
    const int cl_m = tid & 63;
    float c = 0.0f;

    if (tid < 128) ((float*)sh1)[tid] = 0.0f;
    else           ((float*)sh2)[tid - 128] = 0.0f;

    const uint32_t a_h1s0 = (uint32_t)__cvta_generic_to_shared(&sh1[0][0]);
    const uint32_t a_h1s1 = (uint32_t)__cvta_generic_to_shared(&sh1[1][0]);
    const uint32_t a_h2s0 = (uint32_t)__cvta_generic_to_shared(&sh2[0][0]);
    const uint32_t a_h2s1 = (uint32_t)__cvta_generic_to_shared(&sh2[1][0]);
    float* h2out = &g_h2[(size_t)(b0 + cl_b) * TSTEPS * HID + cl_m];
    __syncthreads();

    #pragma unroll 1
    for (int t = 0; t <= TSTEPS; t++) {
        // ---- gate phase: 6 dot products, 192 fma2, 64 LDS.128 (all broadcast)
        u64 A0 = 0, A1 = 0, B0 = 0, B1 = 0, C0 = 0, C1 = 0;
        #pragma unroll
        for (int kk = 0; kk < 16; kk++) {
            u64 p0, p1, q0, q1, r0, r1, s0, s1;
            lds2(p0, p1, a_h1s0 + kk * 16);
            lds2(q0, q1, a_h1s1 + kk * 16);
            lds2(r0, r1, a_h2s0 + kk * 16);
            lds2(s0, s1, a_h2s1 + kk * 16);
            A0 = fma2(w0[2*kk],     p0, A0);
            A0 = fma2(w0[2*kk + 1], p1, A0);
            A1 = fma2(w0[2*kk],     q0, A1);
            A1 = fma2(w0[2*kk + 1], q1, A1);
            B0 = fma2(wA[2*kk],     p0, B0);
            B0 = fma2(wA[2*kk + 1], p1, B0);
            B1 = fma2(wA[2*kk],     q0, B1);
            B1 = fma2(wA[2*kk + 1], q1, B1);
            C0 = fma2(wB[2*kk],     r0, C0);
            C0 = fma2(wB[2*kk + 1], r1, C0);
            C1 = fma2(wB[2*kk],     s0, C1);
            C1 = fma2(wB[2*kk + 1], s1, C1);
        }
        const int tx = (t < TSTEPS) ? t : (TSTEPS - 1);
        float xa0 = sx[0][tx*3 + 0], xa1 = sx[0][tx*3 + 1], xa2 = sx[0][tx*3 + 2];
        float xb0 = sx[1][tx*3 + 0], xb1 = sx[1][tx*3 + 1], xb2 = sx[1][tx*3 + 2];
        float2 fA0 = unpackf2(A0), fA1 = unpackf2(A1);
        float2 fB0 = unpackf2(B0), fB1 = unpackf2(B1);
        float2 fC0 = unpackf2(C0), fC1 = unpackf2(C1);
        float pre10 = fA0.x + fA0.y + bias0 + wx0*xa0 + wx1*xa1 + wx2*xa2;
        float pre11 = fA1.x + fA1.y + bias0 + wx0*xb0 + wx1*xb1 + wx2*xb2;
        float pre20 = (fB0.x + fB0.y) + (fC0.x + fC0.y) + bias1;
        float pre21 = (fB1.x + fB1.y) + (fC1.x + fC1.y) + bias1;
        float v10, v11, v20, v21;
        if (gtype == 2) {
            v10 = tanha(pre10); v11 = tanha(pre11);
            v20 = tanha(pre20); v21 = tanha(pre21);
        } else {
            v10 = siga(pre10); v11 = siga(pre11);
            v20 = siga(pre20); v21 = siga(pre21);
        }
        sg1[0][tid] = v10; sg1[1][tid] = v11;
        sg2[0][tid] = v20; sg2[1][tid] = v21;
        __syncthreads();

        // ---- cell phase: one cell per thread (warp-uniform roles) ----
        bool active = cl_layer ? (t >= 1) : (t < TSTEPS);
        if (active) {
            const float* Gp = cl_layer ? sg2[cl_b] : sg1[cl_b];
            float iv = Gp[cl_m], fv = Gp[cl_m + 64];
            float gv = Gp[cl_m + 128], ov = Gp[cl_m + 192];
            c = fmaf(fv, c, iv * gv);
            float hn = ov * tanha(c);
            if (cl_layer) {
                sh2[cl_b][cl_m] = hn;
                h2out[(size_t)(t - 1) * HID] = hn;
            } else {
                sh1[cl_b][cl_m] = hn;
            }
        }
        __syncthreads();
    }
}

// ============================================================================
// Output projection, fp32 + MLP=8: each thread owns one float4 segment of 8
// different rows; all 8 LDG.128 issued up front (independent -> MLP=8), then
// 8x {3 dots + 16-lane shuffle reduce + store}. 2048 CTAs x 256 threads.
// ============================================================================
#define PROJ_GROUPS (BATCH * TSTEPS / 8)   // 32768 row-groups of 8 rows
__global__ void __launch_bounds__(256) proj_kernel(
    const float* __restrict__ Wout, const float* __restrict__ bout,
    float* __restrict__ y)
{
    __shared__ float sw[3 * 64];
    __shared__ float sb[3];
    const int tid = threadIdx.x;
    if (tid < 192) sw[tid] = Wout[tid];
    if (tid < 3)   sb[tid] = bout[tid];
    __syncthreads();

    const int gg = blockIdx.x * 256 + tid;   // 524288 threads
    const int grp = gg >> 4;                  // row-group 0..32767
    const int l = gg & 15;                    // 16 lanes per row

    // issue all 8 loads up front (independent -> MLP=8)
    float4 hv[8];
    #pragma unroll
    for (int k = 0; k < 8; k++) {
        size_t r = (size_t)grp + (size_t)k * PROJ_GROUPS;
        hv[k] = *(const float4*)&g_h2[r * HID + l * 4];
    }

    const int s4 = l * 4;
    const float* w0r = &sw[s4];
    const float* w1r = &sw[64 + s4];
    const float* w2r = &sw[128 + s4];

    #pragma unroll
    for (int k = 0; k < 8; k++) {
        float4 v = hv[k];
        float a0 = w0r[0]*v.x + w0r[1]*v.y + w0r[2]*v.z + w0r[3]*v.w;
        float a1 = w1r[0]*v.x + w1r[1]*v.y + w1r[2]*v.z + w1r[3]*v.w;
        float a2 = w2r[0]*v.x + w2r[1]*v.y + w2r[2]*v.z + w2r[3]*v.w;
        #pragma unroll
        for (int o = 8; o > 0; o >>= 1) {
            a0 += __shfl_xor_sync(0xffffffffu, a0, o);
            a1 += __shfl_xor_sync(0xffffffffu, a1, o);
            a2 += __shfl_xor_sync(0xffffffffu, a2, o);
        }
        if (l == 0) {
            size_t r = (size_t)grp + (size_t)k * PROJ_GROUPS;
            y[r * 3 + 0] = a0 + sb[0];
            y[r * 3 + 1] = a1 + sb[1];
            y[r * 3 + 2] = a2 + sb[2];
        }
    }
}

extern "C" void kernel_launch(void* const* d_in, const int* in_sizes, int n_in,
                              void* d_out, int out_size)
{
    const float* x    = (const float*)d_in[0];
    const float* Wih0 = (const float*)d_in[1];
    const float* Whh0 = (const float*)d_in[2];
    const float* bih0 = (const float*)d_in[3];
    const float* bhh0 = (const float*)d_in[4];
    const float* Wih1 = (const float*)d_in[5];
    const float* Whh1 = (const float*)d_in[6];
    const float* bih1 = (const float*)d_in[7];
    const float* bhh1 = (const float*)d_in[8];
    const float* Wout = (const float*)d_in[9];
    const float* bout = (const float*)d_in[10];
    float* y = (float*)d_out;

    lstm_fused<<<BATCH / 2, 256>>>(x, Wih0, Whh0, bih0, bhh0,
                                   Wih1, Whh1, bih1, bhh1);
    proj_kernel<<<(BATCH * TSTEPS * 16) / 8 / 256, 256>>>(Wout, bout, y);
}